// round 5
// baseline (speedup 1.0000x reference)
#include <cuda_runtime.h>
#include <math_constants.h>

#define NP 128           // particles
#define NB 512           // batch
#define NH 512           // hidden
#define PB (NP*NB)       // 65536
#define CQ 0.00390625f   // (1-alpha)/P = 0.5/128

// threefry key from jax.random.key(42): (k0=0, k1=42)
#define KS0 0u
#define KS1 42u
#define KS2 (KS0 ^ KS1 ^ 0x1BD11BDAu)

#define TFROUND(r) { x0 += x1; x1 = __funnelshift_l(x1, x1, (r)); x1 ^= x0; }

// jax partitionable threefry: counter (hi=0, lo=i), output = lane0 ^ lane1.
// (bit-exact vs passing rounds; do not modify)
__device__ __forceinline__ unsigned tf_bits(unsigned i) {
    unsigned x0 = KS0;
    unsigned x1 = i + KS1;
    TFROUND(13) TFROUND(15) TFROUND(26) TFROUND(6)
    x0 += KS1; x1 += KS2 + 1u;
    TFROUND(17) TFROUND(29) TFROUND(16) TFROUND(24)
    x0 += KS2; x1 += KS0 + 2u;
    TFROUND(13) TFROUND(15) TFROUND(26) TFROUND(6)
    x0 += KS0; x1 += KS1 + 3u;
    TFROUND(17) TFROUND(29) TFROUND(16) TFROUND(24)
    x0 += KS1; x1 += KS2 + 4u;
    TFROUND(13) TFROUND(15) TFROUND(26) TFROUND(6)
    x0 += KS2; x1 += KS0 + 5u;
    return x0 ^ x1;
}

__device__ __forceinline__ float gumbel_from_bits(unsigned bits) {
    unsigned fb = (bits >> 9) | 0x3f800000u;
    float f = __uint_as_float(fb) - 1.0f;
    float u = fmaxf(f, 1.17549435082228751e-38f);
    return -logf(-logf(u));
}

// ONE kernel: block b owns batch column b.
//   phase 1: lt[p] = log(0.5*exp(prob[p,b]) + 1/256) into smem (threads 0..127)
//   phase 2: warp w samples draws s = w*16..w*16+15 (pairs for ILP) and gathers rows
//   phase 3: per-column reweight + logsumexp -> prob_new
__global__ __launch_bounds__(256) void fused_kernel(
        const float* __restrict__ particles,
        const float* __restrict__ prob,
        float* __restrict__ out_particles,
        float* __restrict__ out_prob) {
    __shared__ float sh_lt[NP];
    __shared__ int   sh_bp[NP];
    __shared__ float red[NP];

    int b    = blockIdx.x;
    int t    = threadIdx.x;
    int w    = t >> 5;
    int lane = t & 31;

    // phase 1 — identical arithmetic to the old logits_kernel
    if (t < NP) {
        float pr = prob[t * NB + b];
        sh_lt[t] = logf(0.5f * expf(pr) + CQ);
    }
    __syncthreads();

    const float4* pf4 = (const float4*)particles;

    // phase 2 — 16 draws per warp, two at a time (8 threefry chains + 8 f4 loads in flight)
    #pragma unroll 1
    for (int k = 0; k < 16; k += 2) {
        int s0 = w * 16 + k;                                // draw s0 and s0+1
        unsigned base0 = ((unsigned)s0 * NB + (unsigned)b) * 128u;
        unsigned base1 = base0 + 65536u;                    // (s0+1)*NB*128

        float best0 = -CUDART_INF_F, best1 = -CUDART_INF_F;
        int bp0 = 0, bp1 = 0;
        #pragma unroll
        for (int j = 0; j < 4; j++) {
            int p = lane + 32 * j;
            unsigned bitsA = tf_bits(base0 + (unsigned)p);
            unsigned bitsB = tf_bits(base1 + (unsigned)p);
            float ltp = sh_lt[p];
            float v0 = gumbel_from_bits(bitsA) + ltp;
            float v1 = gumbel_from_bits(bitsB) + ltp;
            if (v0 > best0) { best0 = v0; bp0 = p; }        // p ascending -> first-max kept
            if (v1 > best1) { best1 = v1; bp1 = p; }
        }
        #pragma unroll
        for (int off = 16; off > 0; off >>= 1) {
            float ov0 = __shfl_xor_sync(0xffffffffu, best0, off);
            int   op0 = __shfl_xor_sync(0xffffffffu, bp0, off);
            float ov1 = __shfl_xor_sync(0xffffffffu, best1, off);
            int   op1 = __shfl_xor_sync(0xffffffffu, bp1, off);
            if (ov0 > best0 || (ov0 == best0 && op0 < bp0)) { best0 = ov0; bp0 = op0; }
            if (ov1 > best1 || (ov1 == best1 && op1 < bp1)) { best1 = ov1; bp1 = op1; }
        }
        if (lane == 0) {
            sh_bp[s0]     = bp0;
            sh_bp[s0 + 1] = bp1;
        }

        // gather: 2 rows x 512 floats, 8 independent float4 per lane
        const float4* src0 = pf4 + ((size_t)bp0 * NB + b) * (NH / 4);
        const float4* src1 = pf4 + ((size_t)bp1 * NB + b) * (NH / 4);
        float4* dst0 = (float4*)out_particles + ((size_t)s0 * NB + b) * (NH / 4);
        float4* dst1 = dst0 + (size_t)NB * (NH / 4);
        float4 a0 = src0[lane];
        float4 a1 = src0[lane + 32];
        float4 a2 = src0[lane + 64];
        float4 a3 = src0[lane + 96];
        float4 c0 = src1[lane];
        float4 c1 = src1[lane + 32];
        float4 c2 = src1[lane + 64];
        float4 c3 = src1[lane + 96];
        dst0[lane]      = a0;
        dst0[lane + 32] = a1;
        dst0[lane + 64] = a2;
        dst0[lane + 96] = a3;
        dst1[lane]      = c0;
        dst1[lane + 32] = c1;
        dst1[lane + 64] = c2;
        dst1[lane + 96] = c3;
    }
    __syncthreads();

    // phase 3 — reference composition: w=exp(p); w2=w/(a*w+c); lw=log(w2); lse over s
    float lw = 0.0f;
    if (t < NP) {
        int idx = sh_bp[t];
        float pg = prob[idx * NB + b];
        float wq = expf(pg);
        float w2 = wq / (0.5f * wq + CQ);
        lw = logf(w2);
        red[t] = lw;
    }
    __syncthreads();
    #pragma unroll
    for (int off = 64; off > 0; off >>= 1) {
        if (t < off) red[t] = fmaxf(red[t], red[t + off]);
        __syncthreads();
    }
    float m = red[0];
    __syncthreads();
    if (t < NP) red[t] = expf(lw - m);
    __syncthreads();
    #pragma unroll
    for (int off = 64; off > 0; off >>= 1) {
        if (t < off) red[t] += red[t + off];
        __syncthreads();
    }
    if (t < NP) {
        float lse = m + logf(red[0]);
        out_prob[t * NB + b] = lw - lse;
    }
}

extern "C" void kernel_launch(void* const* d_in, const int* in_sizes, int n_in,
                              void* d_out, int out_size) {
    const float* particles = (const float*)d_in[0];   // [P*B, H]
    const float* prob      = (const float*)d_in[1];   // [P*B, 1]
    float* out = (float*)d_out;
    float* out_particles = out;                 // [P*B*H]
    float* out_prob = out + (size_t)PB * NH;    // [P*B]

    fused_kernel<<<NB, 256>>>(particles, prob, out_particles, out_prob);
}

// round 6
// speedup vs baseline: 1.1065x; 1.1065x over previous
#include <cuda_runtime.h>
#include <math_constants.h>

#define NP 128           // particles
#define NB 512           // batch
#define NH 512           // hidden
#define PB (NP*NB)       // 65536
#define CQ 0.00390625f   // (1-alpha)/P = 0.5/128

// threefry key from jax.random.key(42): (k0=0, k1=42)
#define KS0 0u
#define KS1 42u
#define KS2 (KS0 ^ KS1 ^ 0x1BD11BDAu)

__device__ int d_idx[PB];   // indices[s*512 + b]

#define TFROUND(r) { x0 += x1; x1 = __funnelshift_l(x1, x1, (r)); x1 ^= x0; }

// jax partitionable threefry: counter (hi=0, lo=i), output = lane0 ^ lane1.
// (bit-exact vs passing rounds; do not modify)
__device__ __forceinline__ unsigned tf_bits(unsigned i) {
    unsigned x0 = KS0;
    unsigned x1 = i + KS1;
    TFROUND(13) TFROUND(15) TFROUND(26) TFROUND(6)
    x0 += KS1; x1 += KS2 + 1u;
    TFROUND(17) TFROUND(29) TFROUND(16) TFROUND(24)
    x0 += KS2; x1 += KS0 + 2u;
    TFROUND(13) TFROUND(15) TFROUND(26) TFROUND(6)
    x0 += KS0; x1 += KS1 + 3u;
    TFROUND(17) TFROUND(29) TFROUND(16) TFROUND(24)
    x0 += KS1; x1 += KS2 + 4u;
    TFROUND(13) TFROUND(15) TFROUND(26) TFROUND(6)
    x0 += KS2; x1 += KS0 + 5u;
    return x0 ^ x1;
}

__device__ __forceinline__ float gumbel_from_bits(unsigned bits) {
    unsigned fb = (bits >> 9) | 0x3f800000u;
    float f = __uint_as_float(fb) - 1.0f;
    float u = fmaxf(f, 1.17549435082228751e-38f);
    return -logf(-logf(u));
}

// K1: block (b, g) owns draws s = g*16 .. g*16+15 of batch column b.
// Phase 1: lt[] in smem.  Phase 2: each warp samples 2 draws (8 threefry
// chains in flight) and gathers both 2KB rows with 8 outstanding float4 loads.
__global__ __launch_bounds__(256) void sample_gather_kernel(
        const float* __restrict__ particles,
        const float* __restrict__ prob,
        float* __restrict__ out_particles) {
    __shared__ float sh_lt[NP];

    int b    = blockIdx.x >> 3;
    int g    = blockIdx.x & 7;
    int t    = threadIdx.x;
    int w    = t >> 5;
    int lane = t & 31;

    if (t < NP) {
        float pr = prob[t * NB + b];
        sh_lt[t] = logf(0.5f * expf(pr) + CQ);   // same expr as passing rounds
    }
    __syncthreads();

    // lt in registers, shared by both draws of this warp
    float lt0 = sh_lt[lane];
    float lt1 = sh_lt[lane + 32];
    float lt2 = sh_lt[lane + 64];
    float lt3 = sh_lt[lane + 96];

    int s0 = g * 16 + w * 2;                       // draws s0, s0+1
    unsigned base0 = (unsigned)s0 * 65536u + (unsigned)b * 128u;  // r*128
    unsigned base1 = base0 + 65536u;

    float best0 = -CUDART_INF_F, best1 = -CUDART_INF_F;
    int bp0 = 0, bp1 = 0;
    #pragma unroll
    for (int j = 0; j < 4; j++) {
        int p = lane + 32 * j;
        float ltp = (j == 0) ? lt0 : (j == 1) ? lt1 : (j == 2) ? lt2 : lt3;
        unsigned bitsA = tf_bits(base0 + (unsigned)p);
        unsigned bitsB = tf_bits(base1 + (unsigned)p);
        float v0 = gumbel_from_bits(bitsA) + ltp;
        float v1 = gumbel_from_bits(bitsB) + ltp;
        if (v0 > best0) { best0 = v0; bp0 = p; }   // p ascending -> first-max kept
        if (v1 > best1) { best1 = v1; bp1 = p; }
    }
    #pragma unroll
    for (int off = 16; off > 0; off >>= 1) {
        float ov0 = __shfl_xor_sync(0xffffffffu, best0, off);
        int   op0 = __shfl_xor_sync(0xffffffffu, bp0, off);
        float ov1 = __shfl_xor_sync(0xffffffffu, best1, off);
        int   op1 = __shfl_xor_sync(0xffffffffu, bp1, off);
        if (ov0 > best0 || (ov0 == best0 && op0 < bp0)) { best0 = ov0; bp0 = op0; }
        if (ov1 > best1 || (ov1 == best1 && op1 < bp1)) { best1 = ov1; bp1 = op1; }
    }
    if (lane == 0) {
        d_idx[s0 * NB + b]       = bp0;
        d_idx[(s0 + 1) * NB + b] = bp1;
    }

    // gather both rows: 8 independent float4 loads in flight, then 8 stores
    const float4* pf4 = (const float4*)particles;
    const float4* srcA = pf4 + ((size_t)bp0 * NB + b) * (NH / 4);
    const float4* srcB = pf4 + ((size_t)bp1 * NB + b) * (NH / 4);
    float4* dstA = (float4*)out_particles + ((size_t)s0 * NB + b) * (NH / 4);
    float4* dstB = dstA + (size_t)NB * (NH / 4);
    float4 a0 = srcA[lane];
    float4 a1 = srcA[lane + 32];
    float4 a2 = srcA[lane + 64];
    float4 a3 = srcA[lane + 96];
    float4 c0 = srcB[lane];
    float4 c1 = srcB[lane + 32];
    float4 c2 = srcB[lane + 64];
    float4 c3 = srcB[lane + 96];
    dstA[lane]      = a0;
    dstA[lane + 32] = a1;
    dstA[lane + 64] = a2;
    dstA[lane + 96] = a3;
    dstB[lane]      = c0;
    dstB[lane + 32] = c1;
    dstB[lane + 64] = c2;
    dstB[lane + 96] = c3;
}

// K2: reweight + per-batch-column logsumexp. One warp per b, 4 s-values per lane.
__global__ __launch_bounds__(256) void probnew_kernel(
        const float* __restrict__ prob, float* __restrict__ out_prob) {
    int b    = (blockIdx.x * 256 + threadIdx.x) >> 5;    // 0..511
    int lane = threadIdx.x & 31;

    float lw[4];
    float m = -CUDART_INF_F;
    #pragma unroll
    for (int k = 0; k < 4; k++) {
        int s = lane + 32 * k;
        int idx = d_idx[s * NB + b];
        float pg = prob[idx * NB + b];
        float w = expf(pg);
        float w2 = w / (0.5f * w + CQ);
        lw[k] = logf(w2);
        m = fmaxf(m, lw[k]);
    }
    #pragma unroll
    for (int off = 16; off > 0; off >>= 1)
        m = fmaxf(m, __shfl_xor_sync(0xffffffffu, m, off));

    float e = 0.0f;
    #pragma unroll
    for (int k = 0; k < 4; k++) e += expf(lw[k] - m);
    #pragma unroll
    for (int off = 16; off > 0; off >>= 1)
        e += __shfl_xor_sync(0xffffffffu, e, off);

    float lse = m + logf(e);
    #pragma unroll
    for (int k = 0; k < 4; k++)
        out_prob[(lane + 32 * k) * NB + b] = lw[k] - lse;
}

extern "C" void kernel_launch(void* const* d_in, const int* in_sizes, int n_in,
                              void* d_out, int out_size) {
    const float* particles = (const float*)d_in[0];   // [P*B, H]
    const float* prob      = (const float*)d_in[1];   // [P*B, 1]
    float* out = (float*)d_out;
    float* out_particles = out;                 // [P*B*H]
    float* out_prob = out + (size_t)PB * NH;    // [P*B]

    sample_gather_kernel<<<NB * 8, 256>>>(particles, prob, out_particles);
    probnew_kernel<<<NB / 8, 256>>>(prob, out_prob);
}

// round 7
// speedup vs baseline: 1.1579x; 1.0464x over previous
#include <cuda_runtime.h>
#include <math_constants.h>

#define NP 128           // particles
#define NB 512           // batch
#define NH 512           // hidden
#define PB (NP*NB)       // 65536
#define CQ 0.00390625f   // (1-alpha)/P = 0.5/128

// threefry key from jax.random.key(42): (k0=0, k1=42)
#define KS0 0u
#define KS1 42u
#define KS2 (KS0 ^ KS1 ^ 0x1BD11BDAu)

__device__ float d_lw[PB];   // d_lw[b*128 + s] = log-weight of draw (s,b), transposed

#define TFROUND(r) { x0 += x1; x1 = __funnelshift_l(x1, x1, (r)); x1 ^= x0; }

// jax partitionable threefry: counter (hi=0, lo=i), output = lane0 ^ lane1.
// (bit-exact vs passing rounds; do not modify)
__device__ __forceinline__ unsigned tf_bits(unsigned i) {
    unsigned x0 = KS0;
    unsigned x1 = i + KS1;
    TFROUND(13) TFROUND(15) TFROUND(26) TFROUND(6)
    x0 += KS1; x1 += KS2 + 1u;
    TFROUND(17) TFROUND(29) TFROUND(16) TFROUND(24)
    x0 += KS2; x1 += KS0 + 2u;
    TFROUND(13) TFROUND(15) TFROUND(26) TFROUND(6)
    x0 += KS0; x1 += KS1 + 3u;
    TFROUND(17) TFROUND(29) TFROUND(16) TFROUND(24)
    x0 += KS1; x1 += KS2 + 4u;
    TFROUND(13) TFROUND(15) TFROUND(26) TFROUND(6)
    x0 += KS2; x1 += KS0 + 5u;
    return x0 ^ x1;
}

__device__ __forceinline__ float gumbel_from_bits(unsigned bits) {
    unsigned fb = (bits >> 9) | 0x3f800000u;
    float f = __uint_as_float(fb) - 1.0f;
    float u = fmaxf(f, 1.17549435082228751e-38f);
    return -logf(-logf(u));
}

// K1: block (b, g) owns draws s = g*16 .. g*16+15 of batch column b.
// Each warp samples 2 draws (8 threefry chains in flight), gathers both 2KB
// rows (8 outstanding float4 loads), and lane 0 emits the reweighted
// log-weight directly (kills the double-indirection in the old probnew).
__global__ __launch_bounds__(256) void sample_gather_kernel(
        const float* __restrict__ particles,
        const float* __restrict__ prob,
        float* __restrict__ out_particles) {
    __shared__ float sh_lt[NP];
    __shared__ float sh_pg[NP];

    int b    = blockIdx.x >> 3;
    int g    = blockIdx.x & 7;
    int t    = threadIdx.x;
    int w    = t >> 5;
    int lane = t & 31;

    if (t < NP) {
        float pr = prob[t * NB + b];
        sh_pg[t] = pr;
        sh_lt[t] = logf(0.5f * expf(pr) + CQ);   // same expr as passing rounds
    }
    __syncthreads();

    // lt in registers, shared by both draws of this warp
    float lt0 = sh_lt[lane];
    float lt1 = sh_lt[lane + 32];
    float lt2 = sh_lt[lane + 64];
    float lt3 = sh_lt[lane + 96];

    int s0 = g * 16 + w * 2;                       // draws s0, s0+1
    unsigned base0 = (unsigned)s0 * 65536u + (unsigned)b * 128u;  // r*128
    unsigned base1 = base0 + 65536u;

    float best0 = -CUDART_INF_F, best1 = -CUDART_INF_F;
    int bp0 = 0, bp1 = 0;
    #pragma unroll
    for (int j = 0; j < 4; j++) {
        int p = lane + 32 * j;
        float ltp = (j == 0) ? lt0 : (j == 1) ? lt1 : (j == 2) ? lt2 : lt3;
        unsigned bitsA = tf_bits(base0 + (unsigned)p);
        unsigned bitsB = tf_bits(base1 + (unsigned)p);
        float v0 = gumbel_from_bits(bitsA) + ltp;
        float v1 = gumbel_from_bits(bitsB) + ltp;
        if (v0 > best0) { best0 = v0; bp0 = p; }   // p ascending -> first-max kept
        if (v1 > best1) { best1 = v1; bp1 = p; }
    }
    #pragma unroll
    for (int off = 16; off > 0; off >>= 1) {
        float ov0 = __shfl_xor_sync(0xffffffffu, best0, off);
        int   op0 = __shfl_xor_sync(0xffffffffu, bp0, off);
        float ov1 = __shfl_xor_sync(0xffffffffu, best1, off);
        int   op1 = __shfl_xor_sync(0xffffffffu, bp1, off);
        if (ov0 > best0 || (ov0 == best0 && op0 < bp0)) { best0 = ov0; bp0 = op0; }
        if (ov1 > best1 || (ov1 == best1 && op1 < bp1)) { best1 = ov1; bp1 = op1; }
    }
    if (lane == 0) {
        // exact reference composition: w=exp(p); w2=w/(a*w+c); lw=log(w2)
        float pg0 = sh_pg[bp0];
        float pg1 = sh_pg[bp1];
        float wq0 = expf(pg0);
        float wq1 = expf(pg1);
        float lw0 = logf(wq0 / (0.5f * wq0 + CQ));
        float lw1 = logf(wq1 / (0.5f * wq1 + CQ));
        d_lw[b * NP + s0]     = lw0;
        d_lw[b * NP + s0 + 1] = lw1;
    }

    // gather both rows: 8 independent float4 loads in flight, then 8 stores
    const float4* pf4 = (const float4*)particles;
    const float4* srcA = pf4 + ((size_t)bp0 * NB + b) * (NH / 4);
    const float4* srcB = pf4 + ((size_t)bp1 * NB + b) * (NH / 4);
    float4* dstA = (float4*)out_particles + ((size_t)s0 * NB + b) * (NH / 4);
    float4* dstB = dstA + (size_t)NB * (NH / 4);
    float4 a0 = srcA[lane];
    float4 a1 = srcA[lane + 32];
    float4 a2 = srcA[lane + 64];
    float4 a3 = srcA[lane + 96];
    float4 c0 = srcB[lane];
    float4 c1 = srcB[lane + 32];
    float4 c2 = srcB[lane + 64];
    float4 c3 = srcB[lane + 96];
    dstA[lane]      = a0;
    dstA[lane + 32] = a1;
    dstA[lane + 64] = a2;
    dstA[lane + 96] = a3;
    dstB[lane]      = c0;
    dstB[lane + 32] = c1;
    dstB[lane + 64] = c2;
    dstB[lane + 96] = c3;
}

// K2: per-batch-column logsumexp over precomputed lw. One warp per b.
// Loads are fully coalesced (d_lw transposed); single load round, shfl reduce.
__global__ __launch_bounds__(256) void probnew_kernel(
        float* __restrict__ out_prob) {
    int b    = (blockIdx.x * 256 + threadIdx.x) >> 5;    // 0..511
    int lane = threadIdx.x & 31;

    const float* lwp = d_lw + b * NP;
    float lw[4];
    float m = -CUDART_INF_F;
    #pragma unroll
    for (int k = 0; k < 4; k++) {
        lw[k] = lwp[lane + 32 * k];
        m = fmaxf(m, lw[k]);
    }
    #pragma unroll
    for (int off = 16; off > 0; off >>= 1)
        m = fmaxf(m, __shfl_xor_sync(0xffffffffu, m, off));

    float e = 0.0f;
    #pragma unroll
    for (int k = 0; k < 4; k++) e += expf(lw[k] - m);
    #pragma unroll
    for (int off = 16; off > 0; off >>= 1)
        e += __shfl_xor_sync(0xffffffffu, e, off);

    float lse = m + logf(e);
    #pragma unroll
    for (int k = 0; k < 4; k++)
        out_prob[(lane + 32 * k) * NB + b] = lw[k] - lse;
}

extern "C" void kernel_launch(void* const* d_in, const int* in_sizes, int n_in,
                              void* d_out, int out_size) {
    const float* particles = (const float*)d_in[0];   // [P*B, H]
    const float* prob      = (const float*)d_in[1];   // [P*B, 1]
    float* out = (float*)d_out;
    float* out_particles = out;                 // [P*B*H]
    float* out_prob = out + (size_t)PB * NH;    // [P*B]

    sample_gather_kernel<<<NB * 8, 256>>>(particles, prob, out_particles);
    probnew_kernel<<<NB / 8, 256>>>(out_prob);
}